// round 2
// baseline (speedup 1.0000x reference)
#include <cuda_runtime.h>
#include <math.h>

#define S_LEN   2048
#define D_DIM   64
#define BH      32
#define BM      128        // query rows per CTA
#define BN      32         // key tile
#define NTILES  (S_LEN / BN)
#define THREADS 128
#define HD      32         // half of D per thread

typedef unsigned long long u64;

// ---- packed f32x2 helpers (sm_103a) ----
__device__ __forceinline__ u64 pack2(float lo, float hi) {
    u64 r; asm("mov.b64 %0, {%1,%2};" : "=l"(r) : "f"(lo), "f"(hi)); return r;
}
__device__ __forceinline__ void unpack2(u64 v, float& a, float& b) {
    asm("mov.b64 {%0,%1}, %2;" : "=f"(a), "=f"(b) : "l"(v));
}
__device__ __forceinline__ u64 ffma2(u64 a, u64 b, u64 c) {
    u64 d; asm("fma.rn.f32x2 %0, %1, %2, %3;" : "=l"(d) : "l"(a), "l"(b), "l"(c)); return d;
}
__device__ __forceinline__ u64 fmul2(u64 a, u64 b) {
    u64 d; asm("mul.rn.f32x2 %0, %1, %2;" : "=l"(d) : "l"(a), "l"(b)); return d;
}
__device__ __forceinline__ u64 fadd2(u64 a, u64 b) {
    u64 d; asm("add.rn.f32x2 %0, %1, %2;" : "=l"(d) : "l"(a), "l"(b)); return d;
}
__device__ __forceinline__ float ex2f(float x) {
    float r; asm("ex2.approx.f32 %0, %1;" : "=f"(r) : "f"(x)); return r;
}

// Layout: lane pair (2p, 2p+1) cooperatively owns query rows rA=2p, rB=2p+1
// within the CTA tile. Even lane holds dims [0,32), odd lane dims [32,64).
// Each thread register-blocks BOTH rows for its half of D:
//   qA/qB: 16 u64 each (32 floats), oA/oB: 16 u64 each.
// One 16B LDS of K feeds 4 FFMA2 (2 rows x 2 pairs) -> LDS traffic halved
// vs the 1-row/full-D layout. Half-dot partials are combined with one
// shfl.bfly(1) per (row,key); softmax is computed redundantly in both lanes.

__global__ void __launch_bounds__(THREADS, 2)
SimpleAttentionModel_39943195853086_kernel(
    const float* __restrict__ Q, const float* __restrict__ K,
    const float* __restrict__ V, const float* __restrict__ dsq,
    float* __restrict__ Out)
{
    __shared__ __align__(16) float Ks[BN * D_DIM];
    __shared__ __align__(16) float Vs[BN * D_DIM];

    const int tid = threadIdx.x;
    const int pr  = tid >> 1;       // pair index 0..63
    const int hf  = tid & 1;        // which half of D
    const int bh  = blockIdx.y;
    const long hbase = (long)bh * S_LEN * D_DIM;

    const int rowA = blockIdx.x * BM + 2 * pr;
    const int rowB = rowA + 1;

    // base-2 softmax: fold log2(e)/sqrt(D) into q
    const float scale = 1.4426950408889634f / dsq[0];
    const u64 scale2 = pack2(scale, scale);

    // q halves in registers: 16 pairs per row
    u64 qA[16], qB[16];
    {
        const ulonglong2* qga = (const ulonglong2*)(Q + hbase + (long)rowA * D_DIM + hf * HD);
        const ulonglong2* qgb = (const ulonglong2*)(Q + hbase + (long)rowB * D_DIM + hf * HD);
        #pragma unroll
        for (int i = 0; i < 8; i++) {
            ulonglong2 va = qga[i];
            ulonglong2 vb = qgb[i];
            qA[2*i]   = fmul2(va.x, scale2);
            qA[2*i+1] = fmul2(va.y, scale2);
            qB[2*i]   = fmul2(vb.x, scale2);
            qB[2*i+1] = fmul2(vb.y, scale2);
        }
    }

    u64 oA[16], oB[16];
    #pragma unroll
    for (int i = 0; i < 16; i++) { oA[i] = 0ull; oB[i] = 0ull; }

    float mA = -1e30f, lA = 0.0f;
    float mB = -1e30f, lB = 0.0f;

    for (int t = 0; t < NTILES; t++) {
        __syncthreads();   // previous tile's PV reads done before overwrite
        // ---- stage K/V tile (row-major, coalesced, conflict-free) ----
        {
            const float4* kg = (const float4*)(K + hbase + (long)t * BN * D_DIM);
            const float4* vg = (const float4*)(V + hbase + (long)t * BN * D_DIM);
            float4* ks4 = (float4*)Ks;
            float4* vs4 = (float4*)Vs;
            #pragma unroll
            for (int i = 0; i < 4; i++) {
                ks4[tid + i * THREADS] = kg[tid + i * THREADS];
                vs4[tid + i * THREADS] = vg[tid + i * THREADS];
            }
        }
        __syncthreads();

        // ---- S = q . K^T for both rows; each 16B K load feeds 4 FFMA2 ----
        float sA[BN], sB[BN];
        #pragma unroll
        for (int kk = 0; kk < BN; kk++) {
            const ulonglong2* kr = (const ulonglong2*)(Ks + kk * D_DIM + hf * HD);
            u64 a0 = 0ull, a1 = 0ull, b0 = 0ull, b1 = 0ull;
            #pragma unroll
            for (int i = 0; i < 8; i++) {
                ulonglong2 kv = kr[i];
                a0 = ffma2(qA[2*i],   kv.x, a0);
                a1 = ffma2(qA[2*i+1], kv.y, a1);
                b0 = ffma2(qB[2*i],   kv.x, b0);
                b1 = ffma2(qB[2*i+1], kv.y, b1);
            }
            float xa, ya, xb, yb;
            unpack2(fadd2(a0, a1), xa, ya);
            unpack2(fadd2(b0, b1), xb, yb);
            float pa = xa + ya;
            float pb = xb + yb;
            // combine half-D partials across the lane pair
            sA[kk] = pa + __shfl_xor_sync(0xffffffffu, pa, 1);
            sB[kk] = pb + __shfl_xor_sync(0xffffffffu, pb, 1);
        }

        // ---- thread-local online softmax, row A ----
        {
            float t0 = sA[0], t1 = sA[1], t2 = sA[2], t3 = sA[3];
            #pragma unroll
            for (int kk = 4; kk < BN; kk += 4) {
                t0 = fmaxf(t0, sA[kk]);   t1 = fmaxf(t1, sA[kk+1]);
                t2 = fmaxf(t2, sA[kk+2]); t3 = fmaxf(t3, sA[kk+3]);
            }
            float tmax = fmaxf(fmaxf(t0, t1), fmaxf(t2, t3));
            float mn = fmaxf(mA, tmax);
            float alpha = ex2f(mA - mn);
            mA = mn;
            u64 al2 = pack2(alpha, alpha);
            #pragma unroll
            for (int i = 0; i < 16; i++) oA[i] = fmul2(oA[i], al2);
            float ls0 = 0.f, ls1 = 0.f, ls2 = 0.f, ls3 = 0.f;
            #pragma unroll
            for (int kk = 0; kk < BN; kk += 4) {
                sA[kk]   = ex2f(sA[kk]   - mn); ls0 += sA[kk];
                sA[kk+1] = ex2f(sA[kk+1] - mn); ls1 += sA[kk+1];
                sA[kk+2] = ex2f(sA[kk+2] - mn); ls2 += sA[kk+2];
                sA[kk+3] = ex2f(sA[kk+3] - mn); ls3 += sA[kk+3];
            }
            lA = lA * alpha + ((ls0 + ls1) + (ls2 + ls3));
        }
        // ---- row B ----
        {
            float t0 = sB[0], t1 = sB[1], t2 = sB[2], t3 = sB[3];
            #pragma unroll
            for (int kk = 4; kk < BN; kk += 4) {
                t0 = fmaxf(t0, sB[kk]);   t1 = fmaxf(t1, sB[kk+1]);
                t2 = fmaxf(t2, sB[kk+2]); t3 = fmaxf(t3, sB[kk+3]);
            }
            float tmax = fmaxf(fmaxf(t0, t1), fmaxf(t2, t3));
            float mn = fmaxf(mB, tmax);
            float alpha = ex2f(mB - mn);
            mB = mn;
            u64 al2 = pack2(alpha, alpha);
            #pragma unroll
            for (int i = 0; i < 16; i++) oB[i] = fmul2(oB[i], al2);
            float ls0 = 0.f, ls1 = 0.f, ls2 = 0.f, ls3 = 0.f;
            #pragma unroll
            for (int kk = 0; kk < BN; kk += 4) {
                sB[kk]   = ex2f(sB[kk]   - mn); ls0 += sB[kk];
                sB[kk+1] = ex2f(sB[kk+1] - mn); ls1 += sB[kk+1];
                sB[kk+2] = ex2f(sB[kk+2] - mn); ls2 += sB[kk+2];
                sB[kk+3] = ex2f(sB[kk+3] - mn); ls3 += sB[kk+3];
            }
            lB = lB * alpha + ((ls0 + ls1) + (ls2 + ls3));
        }

        // ---- O += P @ V; each 16B V load feeds 4 FFMA2 ----
        #pragma unroll
        for (int kk = 0; kk < BN; kk++) {
            u64 pa = pack2(sA[kk], sA[kk]);
            u64 pb = pack2(sB[kk], sB[kk]);
            const ulonglong2* vr = (const ulonglong2*)(Vs + kk * D_DIM + hf * HD);
            #pragma unroll
            for (int i = 0; i < 8; i++) {
                ulonglong2 vv = vr[i];
                oA[2*i]   = ffma2(pa, vv.x, oA[2*i]);
                oA[2*i+1] = ffma2(pa, vv.y, oA[2*i+1]);
                oB[2*i]   = ffma2(pb, vv.x, oB[2*i]);
                oB[2*i+1] = ffma2(pb, vv.y, oB[2*i+1]);
            }
        }
    }

    // ---- epilogue: normalize and store both half-rows ----
    {
        float invA = 1.0f / lA;
        float invB = 1.0f / lB;
        u64 iA = pack2(invA, invA);
        u64 iB = pack2(invB, invB);
        float4* oga = (float4*)(Out + hbase + (long)rowA * D_DIM + hf * HD);
        float4* ogb = (float4*)(Out + hbase + (long)rowB * D_DIM + hf * HD);
        #pragma unroll
        for (int i = 0; i < 8; i++) {
            float a, b, c, d;
            unpack2(fmul2(oA[2*i],   iA), a, b);
            unpack2(fmul2(oA[2*i+1], iA), c, d);
            oga[i] = make_float4(a, b, c, d);
            unpack2(fmul2(oB[2*i],   iB), a, b);
            unpack2(fmul2(oB[2*i+1], iB), c, d);
            ogb[i] = make_float4(a, b, c, d);
        }
    }
}

extern "C" void kernel_launch(void* const* d_in, const int* in_sizes, int n_in,
                              void* d_out, int out_size) {
    const float* Q  = (const float*)d_in[0];
    const float* K  = (const float*)d_in[1];
    const float* V  = (const float*)d_in[2];
    const float* ds = (const float*)d_in[3];
    float* Out = (float*)d_out;

    dim3 grid(S_LEN / BM, BH);
    SimpleAttentionModel_39943195853086_kernel<<<grid, THREADS>>>(Q, K, V, ds, Out);
}

// round 3
// speedup vs baseline: 1.0182x; 1.0182x over previous
#include <cuda_runtime.h>
#include <math.h>

#define S_LEN   2048
#define D_DIM   64
#define BH      32
#define BM      128        // query rows per CTA
#define BN      16         // key tile (small: keeps score regs low)
#define NTILES  (S_LEN / BN)
#define THREADS 128
#define HD      32         // half of D per thread

typedef unsigned long long u64;

// ---- packed f32x2 helpers (sm_103a) ----
__device__ __forceinline__ u64 pack2(float lo, float hi) {
    u64 r; asm("mov.b64 %0, {%1,%2};" : "=l"(r) : "f"(lo), "f"(hi)); return r;
}
__device__ __forceinline__ void unpack2(u64 v, float& a, float& b) {
    asm("mov.b64 {%0,%1}, %2;" : "=f"(a), "=f"(b) : "l"(v));
}
__device__ __forceinline__ u64 ffma2(u64 a, u64 b, u64 c) {
    u64 d; asm("fma.rn.f32x2 %0, %1, %2, %3;" : "=l"(d) : "l"(a), "l"(b), "l"(c)); return d;
}
__device__ __forceinline__ u64 fmul2(u64 a, u64 b) {
    u64 d; asm("mul.rn.f32x2 %0, %1, %2;" : "=l"(d) : "l"(a), "l"(b)); return d;
}
__device__ __forceinline__ u64 fadd2(u64 a, u64 b) {
    u64 d; asm("add.rn.f32x2 %0, %1, %2;" : "=l"(d) : "l"(a), "l"(b)); return d;
}
__device__ __forceinline__ float ex2f(float x) {
    float r; asm("ex2.approx.f32 %0, %1;" : "=f"(r) : "f"(x)); return r;
}

// ---- packed exp2: two elements, zero MUFU ----
// x in (-inf, 0]; clamped to >= -126. Round n=rne(x) via +2^23*1.5 bit trick,
// degree-5 Taylor for 2^f on f in [-0.5,0.5] (rel err ~2.4e-6), then splice n
// into the exponent with integer adds (ALU pipe).
struct Exp2C {
    u64 big, c0, c1, c2, c3, c4, c5;
};
__device__ __forceinline__ Exp2C exp2_init() {
    Exp2C e;
    e.big = pack2(12582912.0f, 12582912.0f);
    e.c0  = pack2(1.0f, 1.0f);
    e.c1  = pack2(0.6931471806f, 0.6931471806f);
    e.c2  = pack2(0.2402265070f, 0.2402265070f);
    e.c3  = pack2(0.0555041087f, 0.0555041087f);
    e.c4  = pack2(0.0096181291f, 0.0096181291f);
    e.c5  = pack2(0.0013333558f, 0.0013333558f);
    return e;
}
__device__ __forceinline__ void exp2_pair(const Exp2C& e, float x0, float x1,
                                          float& r0, float& r1) {
    x0 = fmaxf(x0, -126.0f);
    x1 = fmaxf(x1, -126.0f);
    u64 X = pack2(x0, x1);
    u64 Z = fadd2(X, e.big);                       // bits(z) = 0x4B400000 + n
    u64 NF = fadd2(Z, e.big ^ 0x8000000080000000ULL); // n as float (z - big)
    u64 F  = fadd2(X, NF ^ 0x8000000080000000ULL);    // f = x - n
    u64 P = ffma2(e.c5, F, e.c4);
    P = ffma2(P, F, e.c3);
    P = ffma2(P, F, e.c2);
    P = ffma2(P, F, e.c1);
    P = ffma2(P, F, e.c0);
    float p0, p1, z0, z1;
    unpack2(P, p0, p1);
    unpack2(Z, z0, z1);
    r0 = __int_as_float(__float_as_int(p0) + (__float_as_int(z0) << 23));
    r1 = __int_as_float(__float_as_int(p1) + (__float_as_int(z1) << 23));
}

// Layout: lane pair (2p,2p+1) owns query rows rA=2p, rB=2p+1. Even lane holds
// dims [0,32), odd lane [32,64). Each 16B K/V LDS feeds 4 FFMA2 (2 rows x 2
// pairs). Half-D dot partials combined with one shfl.bfly(1) per (row,key).

__global__ void __launch_bounds__(THREADS, 2)
SimpleAttentionModel_39943195853086_kernel(
    const float* __restrict__ Q, const float* __restrict__ K,
    const float* __restrict__ V, const float* __restrict__ dsq,
    float* __restrict__ Out)
{
    __shared__ __align__(16) float Ks[BN * D_DIM];
    __shared__ __align__(16) float Vs[BN * D_DIM];

    const int tid = threadIdx.x;
    const int pr  = tid >> 1;
    const int hf  = tid & 1;
    const int bh  = blockIdx.y;
    const long hbase = (long)bh * S_LEN * D_DIM;

    const int rowA = blockIdx.x * BM + 2 * pr;
    const int rowB = rowA + 1;

    const Exp2C ec = exp2_init();

    // base-2 softmax: fold log2(e)/sqrt(D) into q
    const float scale = 1.4426950408889634f / dsq[0];
    const u64 scale2 = pack2(scale, scale);

    u64 qA[16], qB[16];
    {
        const ulonglong2* qga = (const ulonglong2*)(Q + hbase + (long)rowA * D_DIM + hf * HD);
        const ulonglong2* qgb = (const ulonglong2*)(Q + hbase + (long)rowB * D_DIM + hf * HD);
        #pragma unroll
        for (int i = 0; i < 8; i++) {
            ulonglong2 va = qga[i];
            ulonglong2 vb = qgb[i];
            qA[2*i]   = fmul2(va.x, scale2);
            qA[2*i+1] = fmul2(va.y, scale2);
            qB[2*i]   = fmul2(vb.x, scale2);
            qB[2*i+1] = fmul2(vb.y, scale2);
        }
    }

    u64 oA[16], oB[16];
    #pragma unroll
    for (int i = 0; i < 16; i++) { oA[i] = 0ull; oB[i] = 0ull; }

    float mA = -1e30f, lA = 0.0f;
    float mB = -1e30f, lB = 0.0f;

    for (int t = 0; t < NTILES; t++) {
        __syncthreads();
        // ---- stage K/V tile (16 rows x 64 f32 = 4KB each) ----
        {
            const float4* kg = (const float4*)(K + hbase + (long)t * BN * D_DIM);
            const float4* vg = (const float4*)(V + hbase + (long)t * BN * D_DIM);
            float4* ks4 = (float4*)Ks;
            float4* vs4 = (float4*)Vs;
            #pragma unroll
            for (int i = 0; i < 2; i++) {
                ks4[tid + i * THREADS] = kg[tid + i * THREADS];
                vs4[tid + i * THREADS] = vg[tid + i * THREADS];
            }
        }
        __syncthreads();

        // ---- S = q . K^T (half-D per lane; 4 FFMA2 per 16B LDS) ----
        float sA[BN], sB[BN];
        #pragma unroll
        for (int kk = 0; kk < BN; kk++) {
            const ulonglong2* kr = (const ulonglong2*)(Ks + kk * D_DIM + hf * HD);
            u64 a0 = 0ull, a1 = 0ull, b0 = 0ull, b1 = 0ull;
            #pragma unroll
            for (int i = 0; i < 8; i++) {
                ulonglong2 kv = kr[i];
                a0 = ffma2(qA[2*i],   kv.x, a0);
                a1 = ffma2(qA[2*i+1], kv.y, a1);
                b0 = ffma2(qB[2*i],   kv.x, b0);
                b1 = ffma2(qB[2*i+1], kv.y, b1);
            }
            float xa, ya, xb, yb;
            unpack2(fadd2(a0, a1), xa, ya);
            unpack2(fadd2(b0, b1), xb, yb);
            float pa = xa + ya;
            float pb = xb + yb;
            sA[kk] = pa + __shfl_xor_sync(0xffffffffu, pa, 1);
            sB[kk] = pb + __shfl_xor_sync(0xffffffffu, pb, 1);
        }

        // ---- online softmax row A (exp via packed poly, no MUFU) ----
        {
            float t0 = fmaxf(sA[0], sA[1]),  t1 = fmaxf(sA[2], sA[3]);
            float t2 = fmaxf(sA[4], sA[5]),  t3 = fmaxf(sA[6], sA[7]);
            float t4 = fmaxf(sA[8], sA[9]),  t5 = fmaxf(sA[10], sA[11]);
            float t6 = fmaxf(sA[12], sA[13]),t7 = fmaxf(sA[14], sA[15]);
            float tmax = fmaxf(fmaxf(fmaxf(t0,t1), fmaxf(t2,t3)),
                               fmaxf(fmaxf(t4,t5), fmaxf(t6,t7)));
            float mn = fmaxf(mA, tmax);
            float alpha = ex2f(mA - mn);
            mA = mn;
            u64 al2 = pack2(alpha, alpha);
            #pragma unroll
            for (int i = 0; i < 16; i++) oA[i] = fmul2(oA[i], al2);
            float ls = 0.f;
            #pragma unroll
            for (int kk = 0; kk < BN; kk += 2) {
                exp2_pair(ec, sA[kk] - mn, sA[kk+1] - mn, sA[kk], sA[kk+1]);
                ls += sA[kk] + sA[kk+1];
            }
            lA = lA * alpha + ls;
        }
        // ---- row B ----
        {
            float t0 = fmaxf(sB[0], sB[1]),  t1 = fmaxf(sB[2], sB[3]);
            float t2 = fmaxf(sB[4], sB[5]),  t3 = fmaxf(sB[6], sB[7]);
            float t4 = fmaxf(sB[8], sB[9]),  t5 = fmaxf(sB[10], sB[11]);
            float t6 = fmaxf(sB[12], sB[13]),t7 = fmaxf(sB[14], sB[15]);
            float tmax = fmaxf(fmaxf(fmaxf(t0,t1), fmaxf(t2,t3)),
                               fmaxf(fmaxf(t4,t5), fmaxf(t6,t7)));
            float mn = fmaxf(mB, tmax);
            float alpha = ex2f(mB - mn);
            mB = mn;
            u64 al2 = pack2(alpha, alpha);
            #pragma unroll
            for (int i = 0; i < 16; i++) oB[i] = fmul2(oB[i], al2);
            float ls = 0.f;
            #pragma unroll
            for (int kk = 0; kk < BN; kk += 2) {
                exp2_pair(ec, sB[kk] - mn, sB[kk+1] - mn, sB[kk], sB[kk+1]);
                ls += sB[kk] + sB[kk+1];
            }
            lB = lB * alpha + ls;
        }

        // ---- O += P @ V (half-D per lane; 4 FFMA2 per 16B LDS) ----
        #pragma unroll
        for (int kk = 0; kk < BN; kk++) {
            u64 pa = pack2(sA[kk], sA[kk]);
            u64 pb = pack2(sB[kk], sB[kk]);
            const ulonglong2* vr = (const ulonglong2*)(Vs + kk * D_DIM + hf * HD);
            #pragma unroll
            for (int i = 0; i < 8; i++) {
                ulonglong2 vv = vr[i];
                oA[2*i]   = ffma2(pa, vv.x, oA[2*i]);
                oA[2*i+1] = ffma2(pa, vv.y, oA[2*i+1]);
                oB[2*i]   = ffma2(pb, vv.x, oB[2*i]);
                oB[2*i+1] = ffma2(pb, vv.y, oB[2*i+1]);
            }
        }
    }

    // ---- epilogue: normalize and store both half-rows ----
    {
        float invA = 1.0f / lA;
        float invB = 1.0f / lB;
        u64 iA = pack2(invA, invA);
        u64 iB = pack2(invB, invB);
        float4* oga = (float4*)(Out + hbase + (long)rowA * D_DIM + hf * HD);
        float4* ogb = (float4*)(Out + hbase + (long)rowB * D_DIM + hf * HD);
        #pragma unroll
        for (int i = 0; i < 8; i++) {
            float a, b, c, d;
            unpack2(fmul2(oA[2*i],   iA), a, b);
            unpack2(fmul2(oA[2*i+1], iA), c, d);
            oga[i] = make_float4(a, b, c, d);
            unpack2(fmul2(oB[2*i],   iB), a, b);
            unpack2(fmul2(oB[2*i+1], iB), c, d);
            ogb[i] = make_float4(a, b, c, d);
        }
    }
}

extern "C" void kernel_launch(void* const* d_in, const int* in_sizes, int n_in,
                              void* d_out, int out_size) {
    const float* Q  = (const float*)d_in[0];
    const float* K  = (const float*)d_in[1];
    const float* V  = (const float*)d_in[2];
    const float* ds = (const float*)d_in[3];
    float* Out = (float*)d_out;

    dim3 grid(S_LEN / BM, BH);
    SimpleAttentionModel_39943195853086_kernel<<<grid, THREADS>>>(Q, K, V, ds, Out);
}

// round 4
// speedup vs baseline: 1.3083x; 1.2850x over previous
#include <cuda_runtime.h>
#include <math.h>

#define S_LEN   2048
#define D_DIM   64
#define BH      32
#define BM      128        // query rows per CTA
#define BN      16         // key tile
#define NTILES  (S_LEN / BN)
#define THREADS 128
#define HD      32         // half of D per thread
#define RSTRIDE 72         // skewed smem row stride (floats): lo@+0, hi@+36

typedef unsigned long long u64;

// ---- packed f32x2 helpers (sm_103a) ----
__device__ __forceinline__ u64 pack2(float lo, float hi) {
    u64 r; asm("mov.b64 %0, {%1,%2};" : "=l"(r) : "f"(lo), "f"(hi)); return r;
}
__device__ __forceinline__ void unpack2(u64 v, float& a, float& b) {
    asm("mov.b64 {%0,%1}, %2;" : "=f"(a), "=f"(b) : "l"(v));
}
__device__ __forceinline__ u64 ffma2(u64 a, u64 b, u64 c) {
    u64 d; asm("fma.rn.f32x2 %0, %1, %2, %3;" : "=l"(d) : "l"(a), "l"(b), "l"(c)); return d;
}
__device__ __forceinline__ u64 fmul2(u64 a, u64 b) {
    u64 d; asm("mul.rn.f32x2 %0, %1, %2;" : "=l"(d) : "l"(a), "l"(b)); return d;
}
__device__ __forceinline__ u64 fadd2(u64 a, u64 b) {
    u64 d; asm("add.rn.f32x2 %0, %1, %2;" : "=l"(d) : "l"(a), "l"(b)); return d;
}
__device__ __forceinline__ float ex2f(float x) {
    float r; asm("ex2.approx.f32 %0, %1;" : "=f"(r) : "f"(x)); return r;
}

// Layout: lane pair (2p,2p+1) owns query rows rA=2p, rB=2p+1. Even lane holds
// dims [0,32), odd lane [32,64). Each 16B K/V LDS feeds 4 FFMA2.
// Smem rows are SKEWED: stride 72 floats, hi-half at +36 floats (144B), so
// even-lane banks (8kk+4i .. +3) and odd-lane banks (8kk+4+4i .. +3) are
// disjoint -> every broadcast-pair LDS.128 is a single wavefront.

__global__ void __launch_bounds__(THREADS, 2)
SimpleAttentionModel_39943195853086_kernel(
    const float* __restrict__ Q, const float* __restrict__ K,
    const float* __restrict__ V, const float* __restrict__ dsq,
    float* __restrict__ Out)
{
    __shared__ __align__(16) float Ks[BN * RSTRIDE];
    __shared__ __align__(16) float Vs[BN * RSTRIDE];

    const int tid = threadIdx.x;
    const int pr  = tid >> 1;
    const int hf  = tid & 1;
    const int bh  = blockIdx.y;
    const long hbase = (long)bh * S_LEN * D_DIM;

    const int rowA = blockIdx.x * BM + 2 * pr;
    const int rowB = rowA + 1;

    // base-2 softmax: fold log2(e)/sqrt(D) into q
    const float scale = 1.4426950408889634f / dsq[0];
    const u64 scale2 = pack2(scale, scale);

    u64 qA[16], qB[16];
    {
        const ulonglong2* qga = (const ulonglong2*)(Q + hbase + (long)rowA * D_DIM + hf * HD);
        const ulonglong2* qgb = (const ulonglong2*)(Q + hbase + (long)rowB * D_DIM + hf * HD);
        #pragma unroll
        for (int i = 0; i < 8; i++) {
            ulonglong2 va = qga[i];
            ulonglong2 vb = qgb[i];
            qA[2*i]   = fmul2(va.x, scale2);
            qA[2*i+1] = fmul2(va.y, scale2);
            qB[2*i]   = fmul2(vb.x, scale2);
            qB[2*i+1] = fmul2(vb.y, scale2);
        }
    }

    u64 oA[16], oB[16];
    #pragma unroll
    for (int i = 0; i < 16; i++) { oA[i] = 0ull; oB[i] = 0ull; }

    float mA = -1e30f, lA = 0.0f;
    float mB = -1e30f, lB = 0.0f;

    // staging dest offsets for this thread's two float4s (skewed layout)
    int stg_off[2], stg_src[2];
    #pragma unroll
    for (int i = 0; i < 2; i++) {
        int idx = tid + i * THREADS;      // float4 index 0..255
        int row = idx >> 4;               // 16 float4 per 64-float row
        int j   = idx & 15;
        stg_src[i] = idx;
        stg_off[i] = row * RSTRIDE + ((j < 8) ? 4 * j : 36 + 4 * (j - 8));
    }

    for (int t = 0; t < NTILES; t++) {
        __syncthreads();
        // ---- stage K/V tile into skewed smem ----
        {
            const float4* kg = (const float4*)(K + hbase + (long)t * BN * D_DIM);
            const float4* vg = (const float4*)(V + hbase + (long)t * BN * D_DIM);
            #pragma unroll
            for (int i = 0; i < 2; i++) {
                *(float4*)(Ks + stg_off[i]) = kg[stg_src[i]];
                *(float4*)(Vs + stg_off[i]) = vg[stg_src[i]];
            }
        }
        __syncthreads();

        // ---- S = q . K^T (half-D per lane; 4 FFMA2 per 16B LDS) ----
        float sA[BN], sB[BN];
        #pragma unroll
        for (int kk = 0; kk < BN; kk++) {
            const ulonglong2* kr = (const ulonglong2*)(Ks + kk * RSTRIDE + hf * 36);
            u64 a0 = 0ull, a1 = 0ull, b0 = 0ull, b1 = 0ull;
            #pragma unroll
            for (int i = 0; i < 8; i++) {
                ulonglong2 kv = kr[i];
                a0 = ffma2(qA[2*i],   kv.x, a0);
                a1 = ffma2(qA[2*i+1], kv.y, a1);
                b0 = ffma2(qB[2*i],   kv.x, b0);
                b1 = ffma2(qB[2*i+1], kv.y, b1);
            }
            float xa, ya, xb, yb;
            unpack2(fadd2(a0, a1), xa, ya);
            unpack2(fadd2(b0, b1), xb, yb);
            float pa = xa + ya;
            float pb = xb + yb;
            sA[kk] = pa + __shfl_xor_sync(0xffffffffu, pa, 1);
            sB[kk] = pb + __shfl_xor_sync(0xffffffffu, pb, 1);
        }

        // ---- online softmax row A ----
        {
            float t0 = fmaxf(sA[0], sA[1]),  t1 = fmaxf(sA[2], sA[3]);
            float t2 = fmaxf(sA[4], sA[5]),  t3 = fmaxf(sA[6], sA[7]);
            float t4 = fmaxf(sA[8], sA[9]),  t5 = fmaxf(sA[10], sA[11]);
            float t6 = fmaxf(sA[12], sA[13]),t7 = fmaxf(sA[14], sA[15]);
            float tmax = fmaxf(fmaxf(fmaxf(t0,t1), fmaxf(t2,t3)),
                               fmaxf(fmaxf(t4,t5), fmaxf(t6,t7)));
            float mn = fmaxf(mA, tmax);
            float alpha = ex2f(mA - mn);
            mA = mn;
            u64 al2 = pack2(alpha, alpha);
            #pragma unroll
            for (int i = 0; i < 16; i++) oA[i] = fmul2(oA[i], al2);
            float ls0 = 0.f, ls1 = 0.f, ls2 = 0.f, ls3 = 0.f;
            #pragma unroll
            for (int kk = 0; kk < BN; kk += 4) {
                sA[kk]   = ex2f(sA[kk]   - mn); ls0 += sA[kk];
                sA[kk+1] = ex2f(sA[kk+1] - mn); ls1 += sA[kk+1];
                sA[kk+2] = ex2f(sA[kk+2] - mn); ls2 += sA[kk+2];
                sA[kk+3] = ex2f(sA[kk+3] - mn); ls3 += sA[kk+3];
            }
            lA = lA * alpha + ((ls0 + ls1) + (ls2 + ls3));
        }
        // ---- row B ----
        {
            float t0 = fmaxf(sB[0], sB[1]),  t1 = fmaxf(sB[2], sB[3]);
            float t2 = fmaxf(sB[4], sB[5]),  t3 = fmaxf(sB[6], sB[7]);
            float t4 = fmaxf(sB[8], sB[9]),  t5 = fmaxf(sB[10], sB[11]);
            float t6 = fmaxf(sB[12], sB[13]),t7 = fmaxf(sB[14], sB[15]);
            float tmax = fmaxf(fmaxf(fmaxf(t0,t1), fmaxf(t2,t3)),
                               fmaxf(fmaxf(t4,t5), fmaxf(t6,t7)));
            float mn = fmaxf(mB, tmax);
            float alpha = ex2f(mB - mn);
            mB = mn;
            u64 al2 = pack2(alpha, alpha);
            #pragma unroll
            for (int i = 0; i < 16; i++) oB[i] = fmul2(oB[i], al2);
            float ls0 = 0.f, ls1 = 0.f, ls2 = 0.f, ls3 = 0.f;
            #pragma unroll
            for (int kk = 0; kk < BN; kk += 4) {
                sB[kk]   = ex2f(sB[kk]   - mn); ls0 += sB[kk];
                sB[kk+1] = ex2f(sB[kk+1] - mn); ls1 += sB[kk+1];
                sB[kk+2] = ex2f(sB[kk+2] - mn); ls2 += sB[kk+2];
                sB[kk+3] = ex2f(sB[kk+3] - mn); ls3 += sB[kk+3];
            }
            lB = lB * alpha + ((ls0 + ls1) + (ls2 + ls3));
        }

        // ---- O += P @ V (half-D per lane; 4 FFMA2 per 16B LDS) ----
        #pragma unroll
        for (int kk = 0; kk < BN; kk++) {
            u64 pa = pack2(sA[kk], sA[kk]);
            u64 pb = pack2(sB[kk], sB[kk]);
            const ulonglong2* vr = (const ulonglong2*)(Vs + kk * RSTRIDE + hf * 36);
            #pragma unroll
            for (int i = 0; i < 8; i++) {
                ulonglong2 vv = vr[i];
                oA[2*i]   = ffma2(pa, vv.x, oA[2*i]);
                oA[2*i+1] = ffma2(pa, vv.y, oA[2*i+1]);
                oB[2*i]   = ffma2(pb, vv.x, oB[2*i]);
                oB[2*i+1] = ffma2(pb, vv.y, oB[2*i+1]);
            }
        }
    }

    // ---- epilogue: normalize and store both half-rows ----
    {
        float invA = 1.0f / lA;
        float invB = 1.0f / lB;
        u64 iA = pack2(invA, invA);
        u64 iB = pack2(invB, invB);
        float4* oga = (float4*)(Out + hbase + (long)rowA * D_DIM + hf * HD);
        float4* ogb = (float4*)(Out + hbase + (long)rowB * D_DIM + hf * HD);
        #pragma unroll
        for (int i = 0; i < 8; i++) {
            float a, b, c, d;
            unpack2(fmul2(oA[2*i],   iA), a, b);
            unpack2(fmul2(oA[2*i+1], iA), c, d);
            oga[i] = make_float4(a, b, c, d);
            unpack2(fmul2(oB[2*i],   iB), a, b);
            unpack2(fmul2(oB[2*i+1], iB), c, d);
            ogb[i] = make_float4(a, b, c, d);
        }
    }
}

extern "C" void kernel_launch(void* const* d_in, const int* in_sizes, int n_in,
                              void* d_out, int out_size) {
    const float* Q  = (const float*)d_in[0];
    const float* K  = (const float*)d_in[1];
    const float* V  = (const float*)d_in[2];
    const float* ds = (const float*)d_in[3];
    float* Out = (float*)d_out;

    dim3 grid(S_LEN / BM, BH);
    SimpleAttentionModel_39943195853086_kernel<<<grid, THREADS>>>(Q, K, V, ds, Out);
}

// round 5
// speedup vs baseline: 1.3913x; 1.0635x over previous
#include <cuda_runtime.h>
#include <math.h>

#define S_LEN   2048
#define D_DIM   64
#define BH      32
#define BM      128        // query rows per CTA
#define BN      16         // key tile
#define NTILES  (S_LEN / BN)
#define THREADS 128
#define HD      32         // half of D per thread
#define RSTRIDE 72         // skewed smem row stride (floats): lo@+0, hi@+36
#define NSTAGE  3
#define STAGEF  (2 * BN * RSTRIDE)   // floats per stage (K tile + V tile)

typedef unsigned long long u64;
typedef unsigned int u32;

// ---- packed f32x2 helpers (sm_103a) ----
__device__ __forceinline__ u64 pack2(float lo, float hi) {
    u64 r; asm("mov.b64 %0, {%1,%2};" : "=l"(r) : "f"(lo), "f"(hi)); return r;
}
__device__ __forceinline__ void unpack2(u64 v, float& a, float& b) {
    asm("mov.b64 {%0,%1}, %2;" : "=f"(a), "=f"(b) : "l"(v));
}
__device__ __forceinline__ u64 ffma2(u64 a, u64 b, u64 c) {
    u64 d; asm("fma.rn.f32x2 %0, %1, %2, %3;" : "=l"(d) : "l"(a), "l"(b), "l"(c)); return d;
}
__device__ __forceinline__ u64 fmul2(u64 a, u64 b) {
    u64 d; asm("mul.rn.f32x2 %0, %1, %2;" : "=l"(d) : "l"(a), "l"(b)); return d;
}
__device__ __forceinline__ u64 fadd2(u64 a, u64 b) {
    u64 d; asm("add.rn.f32x2 %0, %1, %2;" : "=l"(d) : "l"(a), "l"(b)); return d;
}
__device__ __forceinline__ float ex2f(float x) {
    float r; asm("ex2.approx.f32 %0, %1;" : "=f"(r) : "f"(x)); return r;
}
__device__ __forceinline__ void cp16(u32 saddr, const void* g) {
    asm volatile("cp.async.cg.shared.global [%0], [%1], 16;" :: "r"(saddr), "l"(g));
}

// Layout: lane pair (2p,2p+1) owns query rows rA=2p, rB=2p+1. Even lane holds
// dims [0,32), odd lane [32,64). Each 16B K/V LDS feeds 4 FFMA2. Smem rows
// skewed (stride 72, hi-half at +36) -> broadcast-pair LDS.128 conflict-free.
// K/V staged via cp.async into a 3-deep ring; one __syncthreads per tile.

__global__ void __launch_bounds__(THREADS, 2)
SimpleAttentionModel_39943195853086_kernel(
    const float* __restrict__ Q, const float* __restrict__ K,
    const float* __restrict__ V, const float* __restrict__ dsq,
    float* __restrict__ Out)
{
    __shared__ __align__(16) float SB[NSTAGE * STAGEF];

    const int tid = threadIdx.x;
    const int pr  = tid >> 1;
    const int hf  = tid & 1;
    const int bh  = blockIdx.y;
    const long hbase = (long)bh * S_LEN * D_DIM;

    const int rowA = blockIdx.x * BM + 2 * pr;
    const int rowB = rowA + 1;

    // base-2 softmax: fold log2(e)/sqrt(D) into q
    const float scale = 1.4426950408889634f / dsq[0];
    const u64 scale2 = pack2(scale, scale);

    u64 qA[16], qB[16];
    {
        const ulonglong2* qga = (const ulonglong2*)(Q + hbase + (long)rowA * D_DIM + hf * HD);
        const ulonglong2* qgb = (const ulonglong2*)(Q + hbase + (long)rowB * D_DIM + hf * HD);
        #pragma unroll
        for (int i = 0; i < 8; i++) {
            ulonglong2 va = qga[i];
            ulonglong2 vb = qgb[i];
            qA[2*i]   = fmul2(va.x, scale2);
            qA[2*i+1] = fmul2(va.y, scale2);
            qB[2*i]   = fmul2(vb.x, scale2);
            qB[2*i+1] = fmul2(vb.y, scale2);
        }
    }

    u64 oA[16], oB[16];
    #pragma unroll
    for (int i = 0; i < 16; i++) { oA[i] = 0ull; oB[i] = 0ull; }

    float mA = -1e30f, lA = 0.0f;
    float mB = -1e30f, lB = 0.0f;

    // staging dest offsets (floats) for this thread's two 16B chunks per array
    int stg_off[2], stg_src[2];
    #pragma unroll
    for (int i = 0; i < 2; i++) {
        int idx = tid + i * THREADS;      // float4 index 0..255
        int row = idx >> 4;               // 16 float4 per 64-float row
        int j   = idx & 15;
        stg_src[i] = idx * 4;             // float offset in gmem tile
        stg_off[i] = row * RSTRIDE + ((j < 8) ? 4 * j : 36 + 4 * (j - 8));
    }

    const u32 sb_u32 = (u32)__cvta_generic_to_shared(SB);
    const float* kbase = K + hbase;
    const float* vbase = V + hbase;

    // ---- prologue: prefetch tiles 0 and 1 ----
    #pragma unroll
    for (int s = 0; s < 2; s++) {
        const float* kg = kbase + s * (BN * D_DIM);
        const float* vg = vbase + s * (BN * D_DIM);
        u32 kd = sb_u32 + (u32)(s * STAGEF) * 4u;
        u32 vd = kd + (u32)(BN * RSTRIDE) * 4u;
        #pragma unroll
        for (int i = 0; i < 2; i++) {
            cp16(kd + (u32)stg_off[i] * 4u, kg + stg_src[i]);
            cp16(vd + (u32)stg_off[i] * 4u, vg + stg_src[i]);
        }
        asm volatile("cp.async.commit_group;");
    }

    int stage = 0;          // stage holding tile t
    int nstage = 2;         // stage to fill with tile t+2

    for (int t = 0; t < NTILES; t++) {
        // tile t must be complete (pending <= 1 group: tile t+1)
        asm volatile("cp.async.wait_group 1;");
        __syncthreads();

        // prefetch tile t+2 into nstage (safe: everyone is past compute t-1)
        if (t + 2 < NTILES) {
            const float* kg = kbase + (t + 2) * (BN * D_DIM);
            const float* vg = vbase + (t + 2) * (BN * D_DIM);
            u32 kd = sb_u32 + (u32)(nstage * STAGEF) * 4u;
            u32 vd = kd + (u32)(BN * RSTRIDE) * 4u;
            #pragma unroll
            for (int i = 0; i < 2; i++) {
                cp16(kd + (u32)stg_off[i] * 4u, kg + stg_src[i]);
                cp16(vd + (u32)stg_off[i] * 4u, vg + stg_src[i]);
            }
        }
        asm volatile("cp.async.commit_group;");

        const float* Ks = SB + stage * STAGEF;
        const float* Vs = Ks + BN * RSTRIDE;

        // ---- S = q . K^T (half-D per lane; 4 FFMA2 per 16B LDS) ----
        float sA[BN], sB[BN];
        #pragma unroll
        for (int kk = 0; kk < BN; kk++) {
            const ulonglong2* kr = (const ulonglong2*)(Ks + kk * RSTRIDE + hf * 36);
            u64 a0 = 0ull, a1 = 0ull, b0 = 0ull, b1 = 0ull;
            #pragma unroll
            for (int i = 0; i < 8; i++) {
                ulonglong2 kv = kr[i];
                a0 = ffma2(qA[2*i],   kv.x, a0);
                a1 = ffma2(qA[2*i+1], kv.y, a1);
                b0 = ffma2(qB[2*i],   kv.x, b0);
                b1 = ffma2(qB[2*i+1], kv.y, b1);
            }
            float xa, ya, xb, yb;
            unpack2(fadd2(a0, a1), xa, ya);
            unpack2(fadd2(b0, b1), xb, yb);
            float pa = xa + ya;
            float pb = xb + yb;
            sA[kk] = pa + __shfl_xor_sync(0xffffffffu, pa, 1);
            sB[kk] = pb + __shfl_xor_sync(0xffffffffu, pb, 1);
        }

        // ---- online softmax row A ----
        {
            float t0 = fmaxf(sA[0], sA[1]),  t1 = fmaxf(sA[2], sA[3]);
            float t2 = fmaxf(sA[4], sA[5]),  t3 = fmaxf(sA[6], sA[7]);
            float t4 = fmaxf(sA[8], sA[9]),  t5 = fmaxf(sA[10], sA[11]);
            float t6 = fmaxf(sA[12], sA[13]),t7 = fmaxf(sA[14], sA[15]);
            float tmax = fmaxf(fmaxf(fmaxf(t0,t1), fmaxf(t2,t3)),
                               fmaxf(fmaxf(t4,t5), fmaxf(t6,t7)));
            float mn = fmaxf(mA, tmax);
            float alpha = ex2f(mA - mn);
            mA = mn;
            u64 al2 = pack2(alpha, alpha);
            #pragma unroll
            for (int i = 0; i < 16; i++) oA[i] = fmul2(oA[i], al2);
            float ls0 = 0.f, ls1 = 0.f, ls2 = 0.f, ls3 = 0.f;
            #pragma unroll
            for (int kk = 0; kk < BN; kk += 4) {
                sA[kk]   = ex2f(sA[kk]   - mn); ls0 += sA[kk];
                sA[kk+1] = ex2f(sA[kk+1] - mn); ls1 += sA[kk+1];
                sA[kk+2] = ex2f(sA[kk+2] - mn); ls2 += sA[kk+2];
                sA[kk+3] = ex2f(sA[kk+3] - mn); ls3 += sA[kk+3];
            }
            lA = lA * alpha + ((ls0 + ls1) + (ls2 + ls3));
        }
        // ---- row B ----
        {
            float t0 = fmaxf(sB[0], sB[1]),  t1 = fmaxf(sB[2], sB[3]);
            float t2 = fmaxf(sB[4], sB[5]),  t3 = fmaxf(sB[6], sB[7]);
            float t4 = fmaxf(sB[8], sB[9]),  t5 = fmaxf(sB[10], sB[11]);
            float t6 = fmaxf(sB[12], sB[13]),t7 = fmaxf(sB[14], sB[15]);
            float tmax = fmaxf(fmaxf(fmaxf(t0,t1), fmaxf(t2,t3)),
                               fmaxf(fmaxf(t4,t5), fmaxf(t6,t7)));
            float mn = fmaxf(mB, tmax);
            float alpha = ex2f(mB - mn);
            mB = mn;
            u64 al2 = pack2(alpha, alpha);
            #pragma unroll
            for (int i = 0; i < 16; i++) oB[i] = fmul2(oB[i], al2);
            float ls0 = 0.f, ls1 = 0.f, ls2 = 0.f, ls3 = 0.f;
            #pragma unroll
            for (int kk = 0; kk < BN; kk += 4) {
                sB[kk]   = ex2f(sB[kk]   - mn); ls0 += sB[kk];
                sB[kk+1] = ex2f(sB[kk+1] - mn); ls1 += sB[kk+1];
                sB[kk+2] = ex2f(sB[kk+2] - mn); ls2 += sB[kk+2];
                sB[kk+3] = ex2f(sB[kk+3] - mn); ls3 += sB[kk+3];
            }
            lB = lB * alpha + ((ls0 + ls1) + (ls2 + ls3));
        }

        // ---- O += P @ V (half-D per lane; 4 FFMA2 per 16B LDS) ----
        #pragma unroll
        for (int kk = 0; kk < BN; kk++) {
            u64 pa = pack2(sA[kk], sA[kk]);
            u64 pb = pack2(sB[kk], sB[kk]);
            const ulonglong2* vr = (const ulonglong2*)(Vs + kk * RSTRIDE + hf * 36);
            #pragma unroll
            for (int i = 0; i < 8; i++) {
                ulonglong2 vv = vr[i];
                oA[2*i]   = ffma2(pa, vv.x, oA[2*i]);
                oA[2*i+1] = ffma2(pa, vv.y, oA[2*i+1]);
                oB[2*i]   = ffma2(pb, vv.x, oB[2*i]);
                oB[2*i+1] = ffma2(pb, vv.y, oB[2*i+1]);
            }
        }

        stage  = (stage  + 1 == NSTAGE) ? 0 : stage + 1;
        nstage = (nstage + 1 == NSTAGE) ? 0 : nstage + 1;
    }

    // ---- epilogue: normalize and store both half-rows ----
    {
        float invA = 1.0f / lA;
        float invB = 1.0f / lB;
        u64 iA = pack2(invA, invA);
        u64 iB = pack2(invB, invB);
        float4* oga = (float4*)(Out + hbase + (long)rowA * D_DIM + hf * HD);
        float4* ogb = (float4*)(Out + hbase + (long)rowB * D_DIM + hf * HD);
        #pragma unroll
        for (int i = 0; i < 8; i++) {
            float a, b, c, d;
            unpack2(fmul2(oA[2*i],   iA), a, b);
            unpack2(fmul2(oA[2*i+1], iA), c, d);
            oga[i] = make_float4(a, b, c, d);
            unpack2(fmul2(oB[2*i],   iB), a, b);
            unpack2(fmul2(oB[2*i+1], iB), c, d);
            ogb[i] = make_float4(a, b, c, d);
        }
    }
}

extern "C" void kernel_launch(void* const* d_in, const int* in_sizes, int n_in,
                              void* d_out, int out_size) {
    const float* Q  = (const float*)d_in[0];
    const float* K  = (const float*)d_in[1];
    const float* V  = (const float*)d_in[2];
    const float* ds = (const float*)d_in[3];
    float* Out = (float*)d_out;

    dim3 grid(S_LEN / BM, BH);
    SimpleAttentionModel_39943195853086_kernel<<<grid, THREADS>>>(Q, K, V, ds, Out);
}

// round 6
// speedup vs baseline: 4.2814x; 3.0772x over previous
#include <cuda_runtime.h>
#include <cuda_bf16.h>
#include <math.h>

#define S_LEN   2048
#define D_DIM   64
#define BHN     32          // B*H
#define BM      64          // query rows per CTA (4 warps x m16)
#define BN      32          // key tile
#define NT      (S_LEN / BN)
#define THREADS 128

#define ROWB    144         // padded smem row: 72 bf16 = 144 bytes
#define ARRB    (BN * ROWB) // 4608 bytes per array
#define STAGEB  (4 * ARRB)  // K_hi,K_lo,V_hi,V_lo = 18432 bytes
#define KV_ELEMS (2 * 16 * 2048 * 64)

typedef unsigned int u32;

// global bf16 hi/lo scratch for K and V (split once per launch)
__device__ __nv_bfloat16 g_Khi[KV_ELEMS];
__device__ __nv_bfloat16 g_Klo[KV_ELEMS];
__device__ __nv_bfloat16 g_Vhi[KV_ELEMS];
__device__ __nv_bfloat16 g_Vlo[KV_ELEMS];

__device__ __forceinline__ float ex2f(float x) {
    float r; asm("ex2.approx.f32 %0, %1;" : "=f"(r) : "f"(x)); return r;
}
__device__ __forceinline__ void cp16(u32 saddr, const void* g) {
    asm volatile("cp.async.cg.shared.global [%0], [%1], 16;" :: "r"(saddr), "l"(g));
}
__device__ __forceinline__ u32 b2u(__nv_bfloat162 h) {
    return *reinterpret_cast<u32*>(&h);
}
// split (x,y) fp32 pair -> bf16x2 hi + bf16x2 lo  (lo = residual)
__device__ __forceinline__ void split2(float x, float y, u32& hi, u32& lo) {
    __nv_bfloat162 h = __floats2bfloat162_rn(x, y);
    float2 hf = __bfloat1622float2(h);
    __nv_bfloat162 l = __floats2bfloat162_rn(x - hf.x, y - hf.y);
    hi = b2u(h); lo = b2u(l);
}

__device__ __forceinline__ void ldsm4(u32& r0, u32& r1, u32& r2, u32& r3, u32 addr) {
    asm volatile("ldmatrix.sync.aligned.m8n8.x4.shared.b16 {%0,%1,%2,%3}, [%4];"
        : "=r"(r0), "=r"(r1), "=r"(r2), "=r"(r3) : "r"(addr));
}
__device__ __forceinline__ void ldsm4t(u32& r0, u32& r1, u32& r2, u32& r3, u32 addr) {
    asm volatile("ldmatrix.sync.aligned.m8n8.x4.trans.shared.b16 {%0,%1,%2,%3}, [%4];"
        : "=r"(r0), "=r"(r1), "=r"(r2), "=r"(r3) : "r"(addr));
}
__device__ __forceinline__ void mma16816(float* d, const u32* a, u32 b0, u32 b1) {
    asm volatile("mma.sync.aligned.m16n8k16.row.col.f32.bf16.bf16.f32 "
        "{%0,%1,%2,%3}, {%4,%5,%6,%7}, {%8,%9}, {%0,%1,%2,%3};"
        : "+f"(d[0]), "+f"(d[1]), "+f"(d[2]), "+f"(d[3])
        : "r"(a[0]), "r"(a[1]), "r"(a[2]), "r"(a[3]), "r"(b0), "r"(b1));
}

// ---- pre-kernel: split K,V fp32 -> bf16 hi/lo arrays ----
__global__ void __launch_bounds__(256)
cvt_kernel(const float4* __restrict__ K, const float4* __restrict__ V) {
    const int n4 = KV_ELEMS / 4;
    __nv_bfloat162* khi = (__nv_bfloat162*)g_Khi;
    __nv_bfloat162* klo = (__nv_bfloat162*)g_Klo;
    __nv_bfloat162* vhi = (__nv_bfloat162*)g_Vhi;
    __nv_bfloat162* vlo = (__nv_bfloat162*)g_Vlo;
    for (int i = blockIdx.x * blockDim.x + threadIdx.x; i < n4;
         i += gridDim.x * blockDim.x) {
        float4 k = K[i];
        float4 v = V[i];
        u32 h0, h1, l0, l1;
        split2(k.x, k.y, h0, l0); split2(k.z, k.w, h1, l1);
        *(u32*)&khi[2*i] = h0; *(u32*)&khi[2*i+1] = h1;
        *(u32*)&klo[2*i] = l0; *(u32*)&klo[2*i+1] = l1;
        split2(v.x, v.y, h0, l0); split2(v.z, v.w, h1, l1);
        *(u32*)&vhi[2*i] = h0; *(u32*)&vhi[2*i+1] = h1;
        *(u32*)&vlo[2*i] = l0; *(u32*)&vlo[2*i+1] = l1;
    }
}

// ---- main attention kernel (FA2 layout, 3xBF16 mma.sync) ----
__global__ void __launch_bounds__(THREADS, 2)
SimpleAttentionModel_39943195853086_kernel(
    const float* __restrict__ Q, const float* __restrict__ dsq,
    float* __restrict__ Out)
{
    __shared__ __align__(16) unsigned char smem_raw[2 * STAGEB];

    const int tid  = threadIdx.x;
    const int wid  = tid >> 5;
    const int lane = tid & 31;
    const int gr   = lane >> 2;        // 0..7 (row within m16)
    const int c2   = (lane & 3) * 2;   // column pair base
    const int bh   = blockIdx.y;
    const long hb  = (long)bh * S_LEN * D_DIM;

    const int qrow0 = blockIdx.x * BM + wid * 16 + gr;
    const int qrow1 = qrow0 + 8;

    // base-2 softmax: fold log2(e)/sqrt(D) into Q
    const float scale = 1.4426950408889634f / dsq[0];

    // ---- staging plan: 1024 16B-chunks/tile, 8 per thread ----
    u32 dst_off[8]; int arr_id[8]; long src_off[8];
    #pragma unroll
    for (int i = 0; i < 8; i++) {
        int cid = tid + i * THREADS;
        int a   = cid >> 8;
        int rem = cid & 255;
        int r   = rem >> 3;
        int j   = rem & 7;
        arr_id[i]  = a;
        dst_off[i] = (u32)(a * ARRB + r * ROWB + j * 16);
        src_off[i] = (long)r * D_DIM + j * 8;
    }
    const __nv_bfloat16* srcs[4] = { g_Khi + hb, g_Klo + hb, g_Vhi + hb, g_Vlo + hb };
    const u32 smem_u = (u32)__cvta_generic_to_shared(smem_raw);

    // prologue: prefetch tiles 0,1
    #pragma unroll
    for (int s = 0; s < 2; s++) {
        long tb = (long)s * BN * D_DIM;
        u32 sb = smem_u + s * STAGEB;
        #pragma unroll
        for (int i = 0; i < 8; i++)
            cp16(sb + dst_off[i], srcs[arr_id[i]] + tb + src_off[i]);
        asm volatile("cp.async.commit_group;");
    }

    // ---- Q fragments (scaled, split hi/lo), resident whole kernel ----
    u32 qhi[4][4], qlo[4][4];
    {
        const float* q0 = Q + hb + (long)qrow0 * D_DIM;
        const float* q1 = Q + hb + (long)qrow1 * D_DIM;
        #pragma unroll
        for (int k = 0; k < 4; k++) {
            int cb = k * 16 + c2;
            float2 v;
            v = *(const float2*)(q0 + cb);
            split2(v.x * scale, v.y * scale, qhi[k][0], qlo[k][0]);
            v = *(const float2*)(q1 + cb);
            split2(v.x * scale, v.y * scale, qhi[k][1], qlo[k][1]);
            v = *(const float2*)(q0 + cb + 8);
            split2(v.x * scale, v.y * scale, qhi[k][2], qlo[k][2]);
            v = *(const float2*)(q1 + cb + 8);
            split2(v.x * scale, v.y * scale, qhi[k][3], qlo[k][3]);
        }
    }

    float o[8][4];
    #pragma unroll
    for (int i = 0; i < 8; i++)
        #pragma unroll
        for (int j = 0; j < 4; j++) o[i][j] = 0.0f;
    float m0 = -1e30f, m1 = -1e30f, l0 = 0.0f, l1 = 0.0f;

    for (int t = 0; t < NT; t++) {
        asm volatile("cp.async.wait_group 1;");
        __syncthreads();

        const u32 sb = smem_u + (t & 1) * STAGEB;
        const u32 kh = sb, kl = sb + ARRB, vh = sb + 2 * ARRB, vl = sb + 3 * ARRB;

        // ---- S = Q.K^T : 3xBF16 (hi*hi + hi*lo + lo*hi) ----
        float s[4][4];
        #pragma unroll
        for (int i = 0; i < 4; i++)
            #pragma unroll
            for (int j = 0; j < 4; j++) s[i][j] = 0.0f;

        #pragma unroll
        for (int nf = 0; nf < 4; nf++) {
            const u32 krow = (u32)((nf * 8 + (lane & 7)) * ROWB + ((lane >> 3) * 16));
            #pragma unroll
            for (int kp = 0; kp < 2; kp++) {
                u32 bh0, bh1, bh2, bh3, bl0, bl1, bl2, bl3;
                ldsm4(bh0, bh1, bh2, bh3, kh + krow + kp * 64);
                ldsm4(bl0, bl1, bl2, bl3, kl + krow + kp * 64);
                const int k0 = kp * 2, k1 = kp * 2 + 1;
                mma16816(s[nf], qhi[k0], bh0, bh1);
                mma16816(s[nf], qhi[k0], bl0, bl1);
                mma16816(s[nf], qlo[k0], bh0, bh1);
                mma16816(s[nf], qhi[k1], bh2, bh3);
                mma16816(s[nf], qhi[k1], bl2, bl3);
                mma16816(s[nf], qlo[k1], bh2, bh3);
            }
        }

        // ---- online softmax (rows r and r+8) ----
        float mx0 = fmaxf(fmaxf(s[0][0], s[0][1]), fmaxf(s[1][0], s[1][1]));
        mx0 = fmaxf(mx0, fmaxf(fmaxf(s[2][0], s[2][1]), fmaxf(s[3][0], s[3][1])));
        float mx1 = fmaxf(fmaxf(s[0][2], s[0][3]), fmaxf(s[1][2], s[1][3]));
        mx1 = fmaxf(mx1, fmaxf(fmaxf(s[2][2], s[2][3]), fmaxf(s[3][2], s[3][3])));
        mx0 = fmaxf(mx0, __shfl_xor_sync(0xffffffffu, mx0, 1));
        mx0 = fmaxf(mx0, __shfl_xor_sync(0xffffffffu, mx0, 2));
        mx1 = fmaxf(mx1, __shfl_xor_sync(0xffffffffu, mx1, 1));
        mx1 = fmaxf(mx1, __shfl_xor_sync(0xffffffffu, mx1, 2));

        const float nm0 = fmaxf(m0, mx0), nm1 = fmaxf(m1, mx1);
        const float a0 = ex2f(m0 - nm0), a1 = ex2f(m1 - nm1);
        m0 = nm0; m1 = nm1;
        #pragma unroll
        for (int nd = 0; nd < 8; nd++) {
            o[nd][0] *= a0; o[nd][1] *= a0;
            o[nd][2] *= a1; o[nd][3] *= a1;
        }
        float r0 = 0.f, r1 = 0.f;
        #pragma unroll
        for (int nf = 0; nf < 4; nf++) {
            s[nf][0] = ex2f(s[nf][0] - m0); r0 += s[nf][0];
            s[nf][1] = ex2f(s[nf][1] - m0); r0 += s[nf][1];
            s[nf][2] = ex2f(s[nf][2] - m1); r1 += s[nf][2];
            s[nf][3] = ex2f(s[nf][3] - m1); r1 += s[nf][3];
        }
        r0 += __shfl_xor_sync(0xffffffffu, r0, 1);
        r0 += __shfl_xor_sync(0xffffffffu, r0, 2);
        r1 += __shfl_xor_sync(0xffffffffu, r1, 1);
        r1 += __shfl_xor_sync(0xffffffffu, r1, 2);
        l0 = l0 * a0 + r0;
        l1 = l1 * a1 + r1;

        // ---- P fragments (hi/lo) directly from S accumulators ----
        u32 ph[2][4], pl[2][4];
        #pragma unroll
        for (int ks = 0; ks < 2; ks++) {
            split2(s[2*ks][0],   s[2*ks][1],   ph[ks][0], pl[ks][0]);
            split2(s[2*ks][2],   s[2*ks][3],   ph[ks][1], pl[ks][1]);
            split2(s[2*ks+1][0], s[2*ks+1][1], ph[ks][2], pl[ks][2]);
            split2(s[2*ks+1][2], s[2*ks+1][3], ph[ks][3], pl[ks][3]);
        }

        // ---- O += P.V : 3x split, V fragments via ldmatrix.trans ----
        #pragma unroll
        for (int ndp = 0; ndp < 4; ndp++) {
            #pragma unroll
            for (int ks = 0; ks < 2; ks++) {
                const u32 vrow = (u32)((ks * 16 + (lane & 15)) * ROWB
                                       + ((lane >> 4) * 16) + ndp * 32);
                u32 vh0, vh1, vh2, vh3, vl0, vl1, vl2, vl3;
                ldsm4t(vh0, vh1, vh2, vh3, vh + vrow);
                ldsm4t(vl0, vl1, vl2, vl3, vl + vrow);
                mma16816(o[2*ndp],   ph[ks], vh0, vh1);
                mma16816(o[2*ndp],   ph[ks], vl0, vl1);
                mma16816(o[2*ndp],   pl[ks], vh0, vh1);
                mma16816(o[2*ndp+1], ph[ks], vh2, vh3);
                mma16816(o[2*ndp+1], ph[ks], vl2, vl3);
                mma16816(o[2*ndp+1], pl[ks], vh2, vh3);
            }
        }

        __syncthreads();
        if (t + 2 < NT) {
            long tb = (long)(t + 2) * BN * D_DIM;
            u32 db = smem_u + (t & 1) * STAGEB;
            #pragma unroll
            for (int i = 0; i < 8; i++)
                cp16(db + dst_off[i], srcs[arr_id[i]] + tb + src_off[i]);
        }
        asm volatile("cp.async.commit_group;");
    }

    // ---- epilogue ----
    const float i0 = 1.0f / l0;
    const float i1 = 1.0f / l1;
    float* ob = Out + hb;
    #pragma unroll
    for (int nd = 0; nd < 8; nd++) {
        const int col = nd * 8 + c2;
        float2 w0 = make_float2(o[nd][0] * i0, o[nd][1] * i0);
        float2 w1 = make_float2(o[nd][2] * i1, o[nd][3] * i1);
        *(float2*)(ob + (long)qrow0 * D_DIM + col) = w0;
        *(float2*)(ob + (long)qrow1 * D_DIM + col) = w1;
    }
}

extern "C" void kernel_launch(void* const* d_in, const int* in_sizes, int n_in,
                              void* d_out, int out_size) {
    const float* Q  = (const float*)d_in[0];
    const float* K  = (const float*)d_in[1];
    const float* V  = (const float*)d_in[2];
    const float* ds = (const float*)d_in[3];
    float* Out = (float*)d_out;

    cvt_kernel<<<1024, 256>>>((const float4*)K, (const float4*)V);

    dim3 grid(S_LEN / BM, BHN);
    SimpleAttentionModel_39943195853086_kernel<<<grid, THREADS>>>(Q, ds, Out);
}